// round 4
// baseline (speedup 1.0000x reference)
#include <cuda_runtime.h>
#include <cstdint>

#define B_  2
#define S_  2048
#define D_  2048
#define H_  16
#define HD_ 128

// Scratch (device globals: allocation-free per harness rules). 4 x 32MB.
__device__ float g_q[B_ * S_ * D_];
__device__ float g_k[B_ * S_ * D_];
__device__ float g_v[B_ * S_ * D_];
__device__ float g_ctx[B_ * S_ * D_];

// ===========================================================================
// Common mma.sync helpers (m16n8k8 tf32)
// ===========================================================================
__device__ __forceinline__ void mma_tf32(float* d, const uint32_t* a,
                                         const uint32_t* b)
{
    asm volatile(
        "mma.sync.aligned.m16n8k8.row.col.f32.tf32.tf32.f32 "
        "{%0,%1,%2,%3}, {%4,%5,%6,%7}, {%8,%9}, {%0,%1,%2,%3};\n"
        : "+f"(d[0]), "+f"(d[1]), "+f"(d[2]), "+f"(d[3])
        : "r"(a[0]), "r"(a[1]), "r"(a[2]), "r"(a[3]),
          "r"(b[0]), "r"(b[1]));
}

__device__ __forceinline__ void split_tf32(float x, uint32_t& hi, uint32_t& lo)
{
    uint32_t h;
    asm("cvt.rna.tf32.f32 %0, %1;" : "=r"(h) : "f"(x));
    float l = x - __uint_as_float(h);
    asm("cvt.rna.tf32.f32 %0, %1;" : "=r"(lo) : "f"(l));
    hi = h;
}

__device__ __forceinline__ uint32_t cvt_tf32(float x)
{
    uint32_t h;
    asm("cvt.rna.tf32.f32 %0, %1;" : "=r"(h) : "f"(x));
    return h;
}

// ===========================================================================
// TF32 mma.sync GEMM with 3xTF32 (hi/lo split) for fp32-grade accuracy.
// C[M,N] = A[M,K] @ W[N,K]^T + bias[N]
// CTA tile 128x128, BK=32, 256 threads = 8 warps in 2(M)x4(N), warp tile
// 64x32 = 4x4 m16n8k8 fragments. Raw fp32 staged in smem (stride 36 floats:
// bank = (4m+k)%32 -> conflict-free for fragment access), split to tf32
// hi/lo in registers. cp.async double-buffered global->smem fills.
// ===========================================================================
#define BKT  32
#define ASTR 36
#define TILE_F (128 * ASTR)                 // floats per matrix per buffer
#define GEMM_SMEM (4 * TILE_F * 4)          // 2 buffers x (A + B) bytes

__global__ __launch_bounds__(256) void sgemm_tf32(
    const float* __restrict__ A, const float* __restrict__ W,
    const float* __restrict__ bias, float* __restrict__ C,
    int M, int N, int K)
{
    extern __shared__ __align__(16) float smg[];

    const int tid  = threadIdx.x;
    const int warp = tid >> 5;
    const int lane = tid & 31;
    const int gid  = lane >> 2;     // 0..7
    const int tig  = lane & 3;      // 0..3
    const int wm   = (warp >> 2) * 64;   // 0 | 64
    const int wn   = (warp & 3) * 32;    // 0,32,64,96
    const int bm   = blockIdx.y * 128;
    const int bn   = blockIdx.x * 128;

    float acc[4][4][4];
#pragma unroll
    for (int mi = 0; mi < 4; mi++)
#pragma unroll
        for (int ni = 0; ni < 4; ni++)
#pragma unroll
            for (int r = 0; r < 4; r++) acc[mi][ni][r] = 0.0f;

    const int NT = K / BKT;

    auto issue_tile = [&](int t) {
        const int k0  = t * BKT;
        float* SA = smg + (t & 1) * 2 * TILE_F;
        float* SB = SA + TILE_F;
#pragma unroll
        for (int i = 0; i < 4; i++) {
            int idx = tid + i * 256;          // 0..1023
            int m   = idx >> 3;               // 0..127
            int kc  = (idx & 7) << 2;         // 0..28
            const float* ga = A + (size_t)(bm + m) * K + k0 + kc;
            const float* gb = W + (size_t)(bn + m) * K + k0 + kc;
            uint32_t sa = (uint32_t)__cvta_generic_to_shared(SA + m * ASTR + kc);
            uint32_t sb = (uint32_t)__cvta_generic_to_shared(SB + m * ASTR + kc);
            asm volatile("cp.async.cg.shared.global [%0], [%1], 16;\n"
                         :: "r"(sa), "l"(ga));
            asm volatile("cp.async.cg.shared.global [%0], [%1], 16;\n"
                         :: "r"(sb), "l"(gb));
        }
        asm volatile("cp.async.commit_group;\n");
    };

    issue_tile(0);

    for (int t = 0; t < NT; t++) {
        if (t + 1 < NT) {
            issue_tile(t + 1);
            asm volatile("cp.async.wait_group 1;\n");
        } else {
            asm volatile("cp.async.wait_group 0;\n");
        }
        __syncthreads();

        const float* SA = smg + (t & 1) * 2 * TILE_F;
        const float* SB = SA + TILE_F;

#pragma unroll
        for (int ks = 0; ks < 4; ks++) {
            const int kb = ks * 8 + tig;

            uint32_t bhi[4][2], blo[4][2];
#pragma unroll
            for (int ni = 0; ni < 4; ni++) {
                const int nr = wn + ni * 8 + gid;
                split_tf32(SB[nr * ASTR + kb],     bhi[ni][0], blo[ni][0]);
                split_tf32(SB[nr * ASTR + kb + 4], bhi[ni][1], blo[ni][1]);
            }

#pragma unroll
            for (int mi = 0; mi < 4; mi++) {
                const int mr = wm + mi * 16 + gid;
                uint32_t ahi[4], alo[4];
                split_tf32(SA[mr * ASTR + kb],           ahi[0], alo[0]);
                split_tf32(SA[(mr + 8) * ASTR + kb],     ahi[1], alo[1]);
                split_tf32(SA[mr * ASTR + kb + 4],       ahi[2], alo[2]);
                split_tf32(SA[(mr + 8) * ASTR + kb + 4], ahi[3], alo[3]);
#pragma unroll
                for (int ni = 0; ni < 4; ni++) {
                    mma_tf32(acc[mi][ni], ahi, bhi[ni]);  // hi*hi
                    mma_tf32(acc[mi][ni], ahi, blo[ni]);  // hi*lo
                    mma_tf32(acc[mi][ni], alo, bhi[ni]);  // lo*hi
                }
            }
        }
        __syncthreads();
    }

#pragma unroll
    for (int mi = 0; mi < 4; mi++) {
#pragma unroll
        for (int ni = 0; ni < 4; ni++) {
            const int row = bm + wm + mi * 16 + gid;
            const int col = bn + wn + ni * 8 + 2 * tig;
            const float b0 = bias[col];
            const float b1 = bias[col + 1];
            float2 v0 = { acc[mi][ni][0] + b0, acc[mi][ni][1] + b1 };
            float2 v1 = { acc[mi][ni][2] + b0, acc[mi][ni][3] + b1 };
            *(float2*)(C + (size_t)row * N + col)       = v0;
            *(float2*)(C + (size_t)(row + 8) * N + col) = v1;
        }
    }
}

// ---------------------------------------------------------------------------
// RoPE (interleaved pairs) applied in-place to q and k.
// ---------------------------------------------------------------------------
__global__ void rope_kernel(float* __restrict__ q, float* __restrict__ k,
                            const float* __restrict__ cosT,
                            const float* __restrict__ sinT)
{
    int idx = blockIdx.x * blockDim.x + threadIdx.x;   // B*S*H*64 threads
    int i  = idx & 63;
    int h  = (idx >> 6) & (H_ - 1);
    int bs = idx >> 10;                 // b*S + s
    int s  = bs & (S_ - 1);

    float c  = cosT[s * 64 + i];
    float sn = sinT[s * 64 + i];
    size_t base = (size_t)bs * D_ + h * HD_ + 2 * i;

    float q1 = q[base], q2 = q[base + 1];
    q[base]     = q1 * c - q2 * sn;
    q[base + 1] = q1 * sn + q2 * c;
    float k1 = k[base], k2 = k[base + 1];
    k[base]     = k1 * c - k2 * sn;
    k[base + 1] = k1 * sn + k2 * c;
}

// ===========================================================================
// Flash attention (causal) on tensor pipe, m16n8k8 tf32.
// CTA = 128 threads (4 warps), q-tile 64 rows (warp w owns rows w*16..w*16+15).
// QK^T: 3xTF32 (hi/lo). PV: P hi/lo x V single-tf32 (2 passes).
// S-frag -> A-frag rearrangement via warp shfl (no smem round-trip).
// V transposed into smem at load with XOR swizzle (conflict-free ST and LD).
// Smem: Qs[64][132] + Ks[64][132] + Vt[128][68] = 100 KB -> 2 CTAs/SM.
// ===========================================================================
#define QSTRF 132
#define VSTRF 68
#define FLASH_SMEM ((2 * 64 * QSTRF + 128 * VSTRF) * 4)

__device__ __forceinline__ int vsw(int d, int key)
{
    return d * VSTRF + (key ^ (((d >> 3) & 3) << 3));
}

__global__ __launch_bounds__(128) void flash_kernel(
    const float* __restrict__ Qg, const float* __restrict__ Kg,
    const float* __restrict__ Vg, float* __restrict__ Og)
{
    extern __shared__ __align__(16) float sm[];
    float* Qs = sm;                       // [64][132]
    float* Ks = Qs + 64 * QSTRF;          // [64][132]
    float* Vt = Ks + 64 * QSTRF;          // [128][68], swizzled

    const int tid  = threadIdx.x;
    const int warp = tid >> 5;
    const int lane = tid & 31;
    const int gid  = lane >> 2;      // 0..7
    const int tig  = lane & 3;       // 0..3
    const int wq   = warp * 16;      // warp's q-row base within tile
    const int qt   = blockIdx.x;
    const int h    = blockIdx.y;
    const int b    = blockIdx.z;

    const size_t base_bh = (size_t)b * S_ * D_ + (size_t)h * HD_;

    // ---- Load Q tile (64 x 128) ----
#pragma unroll
    for (int i = 0; i < 16; i++) {
        int idx = tid + i * 128;          // 0..2047 float4s
        int r   = idx >> 5;
        int dq  = (idx & 31) << 2;
        *(float4*)&Qs[r * QSTRF + dq] =
            *(const float4*)(Qg + base_bh + (size_t)(qt * 64 + r) * D_ + dq);
    }

    // O accumulator fragments: 16 n-frags (d = nf*8 + 2*tig + {0,1})
    float ofr[16][4];
#pragma unroll
    for (int nf = 0; nf < 16; nf++)
#pragma unroll
        for (int r = 0; r < 4; r++) ofr[nf][r] = 0.0f;

    float m0 = -1e30f, m1 = -1e30f, l0 = 0.0f, l1 = 0.0f;
    const float scale = 0.08838834764831845f;   // 1/sqrt(128)

    for (int kt = 0; kt <= qt; kt++) {
        __syncthreads();   // previous tile's reads of Ks/Vt done

        // ---- Load K tile (64 x 128) ----
#pragma unroll
        for (int i = 0; i < 16; i++) {
            int idx = tid + i * 128;
            int r   = idx >> 5;
            int dq  = (idx & 31) << 2;
            *(float4*)&Ks[r * QSTRF + dq] =
                *(const float4*)(Kg + base_bh + (size_t)(kt * 64 + r) * D_ + dq);
        }
        // ---- Load + transpose V tile -> Vt[d][key] (swizzled) ----
        for (int kk = warp; kk < 64; kk += 4) {
            const float* vrow = Vg + base_bh + (size_t)(kt * 64 + kk) * D_;
#pragma unroll
            for (int j = 0; j < 4; j++) {
                int d = lane + 32 * j;
                Vt[vsw(d, kk)] = vrow[d];
            }
        }
        __syncthreads();

        // ---- S = Q K^T (3xTF32), warp computes 16 rows x 64 keys ----
        float sfr[8][4];
#pragma unroll
        for (int nf = 0; nf < 8; nf++)
#pragma unroll
            for (int r = 0; r < 4; r++) sfr[nf][r] = 0.0f;

#pragma unroll
        for (int ks = 0; ks < 16; ks++) {
            const int kb = ks * 8 + tig;
            uint32_t ahi[4], alo[4];
            split_tf32(Qs[(wq + gid) * QSTRF + kb],         ahi[0], alo[0]);
            split_tf32(Qs[(wq + gid + 8) * QSTRF + kb],     ahi[1], alo[1]);
            split_tf32(Qs[(wq + gid) * QSTRF + kb + 4],     ahi[2], alo[2]);
            split_tf32(Qs[(wq + gid + 8) * QSTRF + kb + 4], ahi[3], alo[3]);
#pragma unroll
            for (int nf = 0; nf < 8; nf++) {
                uint32_t bhi[2], blo[2];
                split_tf32(Ks[(nf * 8 + gid) * QSTRF + kb],     bhi[0], blo[0]);
                split_tf32(Ks[(nf * 8 + gid) * QSTRF + kb + 4], bhi[1], blo[1]);
                mma_tf32(sfr[nf], ahi, bhi);
                mma_tf32(sfr[nf], ahi, blo);
                mma_tf32(sfr[nf], alo, bhi);
            }
        }

        // ---- scale + causal mask (diag tile only) ----
        const bool diag = (kt == qt);
        const int qrow0 = qt * 64 + wq + gid;
        const int qrow1 = qrow0 + 8;
#pragma unroll
        for (int nf = 0; nf < 8; nf++) {
#pragma unroll
            for (int c = 0; c < 2; c++) {
                int key = kt * 64 + nf * 8 + 2 * tig + c;
                float v0 = sfr[nf][c] * scale;
                float v1 = sfr[nf][2 + c] * scale;
                if (diag && key > qrow0) v0 = -1e30f;
                if (diag && key > qrow1) v1 = -1e30f;
                sfr[nf][c]     = v0;
                sfr[nf][2 + c] = v1;
            }
        }

        // ---- online softmax (rows spread over 4 tig lanes) ----
        float mx0 = -1e30f, mx1 = -1e30f;
#pragma unroll
        for (int nf = 0; nf < 8; nf++) {
            mx0 = fmaxf(mx0, fmaxf(sfr[nf][0], sfr[nf][1]));
            mx1 = fmaxf(mx1, fmaxf(sfr[nf][2], sfr[nf][3]));
        }
        mx0 = fmaxf(mx0, __shfl_xor_sync(0xffffffffu, mx0, 1));
        mx0 = fmaxf(mx0, __shfl_xor_sync(0xffffffffu, mx0, 2));
        mx1 = fmaxf(mx1, __shfl_xor_sync(0xffffffffu, mx1, 1));
        mx1 = fmaxf(mx1, __shfl_xor_sync(0xffffffffu, mx1, 2));

        float mn0 = fmaxf(m0, mx0);
        float mn1 = fmaxf(m1, mx1);
        float rs0 = 0.0f, rs1 = 0.0f;
#pragma unroll
        for (int nf = 0; nf < 8; nf++) {
            sfr[nf][0] = __expf(sfr[nf][0] - mn0);
            sfr[nf][1] = __expf(sfr[nf][1] - mn0);
            sfr[nf][2] = __expf(sfr[nf][2] - mn1);
            sfr[nf][3] = __expf(sfr[nf][3] - mn1);
            rs0 += sfr[nf][0] + sfr[nf][1];
            rs1 += sfr[nf][2] + sfr[nf][3];
        }
        rs0 += __shfl_xor_sync(0xffffffffu, rs0, 1);
        rs0 += __shfl_xor_sync(0xffffffffu, rs0, 2);
        rs1 += __shfl_xor_sync(0xffffffffu, rs1, 1);
        rs1 += __shfl_xor_sync(0xffffffffu, rs1, 2);

        float c0 = __expf(m0 - mn0);
        float c1 = __expf(m1 - mn1);
        l0 = l0 * c0 + rs0;
        l1 = l1 * c1 + rs1;
        m0 = mn0;
        m1 = mn1;
#pragma unroll
        for (int nf = 0; nf < 16; nf++) {
            ofr[nf][0] *= c0; ofr[nf][1] *= c0;
            ofr[nf][2] *= c1; ofr[nf][3] *= c1;
        }

        // ---- PV: O += P @ V. A-frags of P from S-frags via shfl. ----
        const int srcA = (gid << 2) | (tig >> 1);
        const int srcB = srcA + 2;
#pragma unroll
        for (int ks = 0; ks < 8; ks++) {
            float p0 = sfr[ks][0], p1 = sfr[ks][1];
            float p2 = sfr[ks][2], p3 = sfr[ks][3];
            float t0 = __shfl_sync(0xffffffffu, p0, srcA);
            float t1 = __shfl_sync(0xffffffffu, p1, srcA);
            float u0 = __shfl_sync(0xffffffffu, p2, srcA);
            float u1 = __shfl_sync(0xffffffffu, p3, srcA);
            float v0 = __shfl_sync(0xffffffffu, p0, srcB);
            float v1 = __shfl_sync(0xffffffffu, p1, srcB);
            float w0 = __shfl_sync(0xffffffffu, p2, srcB);
            float w1 = __shfl_sync(0xffffffffu, p3, srcB);
            bool odd = (tig & 1);
            float a0f = odd ? t1 : t0;
            float a1f = odd ? u1 : u0;
            float a2f = odd ? v1 : v0;
            float a3f = odd ? w1 : w0;

            uint32_t ahi[4], alo[4];
            split_tf32(a0f, ahi[0], alo[0]);
            split_tf32(a1f, ahi[1], alo[1]);
            split_tf32(a2f, ahi[2], alo[2]);
            split_tf32(a3f, ahi[3], alo[3]);

            const int key = ks * 8 + tig;
#pragma unroll
            for (int nf = 0; nf < 16; nf++) {
                const int d = nf * 8 + gid;
                uint32_t bb[2];
                bb[0] = cvt_tf32(Vt[vsw(d, key)]);
                bb[1] = cvt_tf32(Vt[vsw(d, key + 4)]);
                mma_tf32(ofr[nf], ahi, bb);
                mma_tf32(ofr[nf], alo, bb);
            }
        }
    }

    // ---- normalize + store ----
    float inv0 = 1.0f / l0;
    float inv1 = 1.0f / l1;
    const size_t r0 = base_bh + (size_t)(qt * 64 + wq + gid) * D_;
    const size_t r1 = base_bh + (size_t)(qt * 64 + wq + gid + 8) * D_;
#pragma unroll
    for (int nf = 0; nf < 16; nf++) {
        int col = nf * 8 + 2 * tig;
        float2 o0 = { ofr[nf][0] * inv0, ofr[nf][1] * inv0 };
        float2 o1 = { ofr[nf][2] * inv1, ofr[nf][3] * inv1 };
        *(float2*)(Og + r0 + col) = o0;
        *(float2*)(Og + r1 + col) = o1;
    }
}

// ---------------------------------------------------------------------------
extern "C" void kernel_launch(void* const* d_in, const int* in_sizes, int n_in,
                              void* d_out, int out_size)
{
    const float* x  = (const float*)d_in[0];
    const float* wq = (const float*)d_in[1];
    const float* bq = (const float*)d_in[2];
    const float* wk = (const float*)d_in[3];
    const float* bk = (const float*)d_in[4];
    const float* wv = (const float*)d_in[5];
    const float* bv = (const float*)d_in[6];
    const float* wo = (const float*)d_in[7];
    const float* bo = (const float*)d_in[8];
    const float* fc = (const float*)d_in[9];
    const float* fs = (const float*)d_in[10];
    float* out = (float*)d_out;

    float *q, *k, *v, *ctx;
    cudaGetSymbolAddress((void**)&q,   g_q);
    cudaGetSymbolAddress((void**)&k,   g_k);
    cudaGetSymbolAddress((void**)&v,   g_v);
    cudaGetSymbolAddress((void**)&ctx, g_ctx);

    const int M = B_ * S_;
    dim3 gg(D_ / 128, M / 128);   // (N tiles, M tiles)

    cudaFuncSetAttribute(sgemm_tf32,
                         cudaFuncAttributeMaxDynamicSharedMemorySize,
                         GEMM_SMEM);

    sgemm_tf32<<<gg, 256, GEMM_SMEM>>>(x, wq, bq, q, M, D_, D_);
    sgemm_tf32<<<gg, 256, GEMM_SMEM>>>(x, wk, bk, k, M, D_, D_);
    sgemm_tf32<<<gg, 256, GEMM_SMEM>>>(x, wv, bv, v, M, D_, D_);

    int rope_total = B_ * S_ * H_ * (HD_ / 2);
    rope_kernel<<<rope_total / 256, 256>>>(q, k, fc, fs);

    cudaFuncSetAttribute(flash_kernel,
                         cudaFuncAttributeMaxDynamicSharedMemorySize,
                         FLASH_SMEM);
    flash_kernel<<<dim3(S_ / 64, H_, B_), 128, FLASH_SMEM>>>(q, k, v, ctx);

    sgemm_tf32<<<gg, 256, GEMM_SMEM>>>(ctx, wo, bo, out, M, D_, D_);
}

// round 10
// speedup vs baseline: 1.9467x; 1.9467x over previous
#include <cuda_runtime.h>
#include <cstdint>

#define B_  2
#define S_  2048
#define D_  2048
#define H_  16
#define HD_ 128

// Scratch (device globals: allocation-free per harness rules). 4 x 32MB.
__device__ float g_q[B_ * S_ * D_];
__device__ float g_k[B_ * S_ * D_];
__device__ float g_v[B_ * S_ * D_];
__device__ float g_ctx[B_ * S_ * D_];

// ===========================================================================
// Common mma.sync helpers (m16n8k8 tf32).
// ===========================================================================
__device__ __forceinline__ void mma_tf32(float* d, const uint32_t* a,
                                         const uint32_t* b)
{
    asm volatile(
        "mma.sync.aligned.m16n8k8.row.col.f32.tf32.tf32.f32 "
        "{%0,%1,%2,%3}, {%4,%5,%6,%7}, {%8,%9}, {%0,%1,%2,%3};\n"
        : "+f"(d[0]), "+f"(d[1]), "+f"(d[2]), "+f"(d[3])
        : "r"(a[0]), "r"(a[1]), "r"(a[2]), "r"(a[3]),
          "r"(b[0]), "r"(b[1]));
}

__device__ __forceinline__ uint32_t cvt_tf32(float x)
{
    uint32_t h;
    asm("cvt.rna.tf32.f32 %0, %1;" : "=r"(h) : "f"(x));
    return h;
}

__device__ __forceinline__ void split_tf32(float x, uint32_t& hi, uint32_t& lo)
{
    uint32_t h;
    asm("cvt.rna.tf32.f32 %0, %1;" : "=r"(h) : "f"(x));
    float l = x - __uint_as_float(h);
    asm("cvt.rna.tf32.f32 %0, %1;" : "=r"(lo) : "f"(l));
    hi = h;
}

// ===========================================================================
// TF32 mma.sync GEMM.  C[M,N] = A[M,K] @ W[N,K]^T + bias[N]
// CTA tile 128x128, BK=32, 256 threads = 8 warps in 2(M)x4(N), warp tile
// 64x32 = 4x4 m16n8k8 fragments. Raw fp32 staged in smem (stride 36 floats:
// bank = (4m+k)%32 -> conflict-free for fragment access). cp.async
// double-buffered global->smem fills.
// TRIPLE=false: single-pass tf32 (QKV projections; RoPE fused in epilogue).
// TRIPLE=true : 3xTF32 hi/lo split, fp32-grade (O projection).
// ===========================================================================
#define BKT  32
#define ASTR 36
#define TILE_F (128 * ASTR)                 // floats per matrix per buffer
#define GEMM_SMEM (4 * TILE_F * 4)          // 2 buffers x (A + B) bytes

struct GemmSet {
    const float* W[3];
    const float* bias[3];
    float*       C[3];
};

template <bool TRIPLE>
__device__ __forceinline__ void sgemm_body(
    const float* __restrict__ A, const float* __restrict__ W,
    const float* __restrict__ bias, float* __restrict__ C,
    int M, int N, int K, float* smg,
    const float* __restrict__ cosT, const float* __restrict__ sinT,
    bool do_rope)
{
    const int tid  = threadIdx.x;
    const int warp = tid >> 5;
    const int lane = tid & 31;
    const int gid  = lane >> 2;     // 0..7
    const int tig  = lane & 3;      // 0..3
    const int wm   = (warp >> 2) * 64;   // 0 | 64
    const int wn   = (warp & 3) * 32;    // 0,32,64,96
    const int bm   = blockIdx.y * 128;
    const int bn   = blockIdx.x * 128;

    float acc[4][4][4];
#pragma unroll
    for (int mi = 0; mi < 4; mi++)
#pragma unroll
        for (int ni = 0; ni < 4; ni++)
#pragma unroll
            for (int r = 0; r < 4; r++) acc[mi][ni][r] = 0.0f;

    const int NT = K / BKT;

    auto issue_tile = [&](int t) {
        const int k0  = t * BKT;
        float* SA = smg + (t & 1) * 2 * TILE_F;
        float* SB = SA + TILE_F;
#pragma unroll
        for (int i = 0; i < 4; i++) {
            int idx = tid + i * 256;          // 0..1023
            int m   = idx >> 3;               // 0..127
            int kc  = (idx & 7) << 2;         // 0..28
            const float* ga = A + (size_t)(bm + m) * K + k0 + kc;
            const float* gb = W + (size_t)(bn + m) * K + k0 + kc;
            uint32_t sa = (uint32_t)__cvta_generic_to_shared(SA + m * ASTR + kc);
            uint32_t sb = (uint32_t)__cvta_generic_to_shared(SB + m * ASTR + kc);
            asm volatile("cp.async.cg.shared.global [%0], [%1], 16;\n"
                         :: "r"(sa), "l"(ga));
            asm volatile("cp.async.cg.shared.global [%0], [%1], 16;\n"
                         :: "r"(sb), "l"(gb));
        }
        asm volatile("cp.async.commit_group;\n");
    };

    issue_tile(0);

    for (int t = 0; t < NT; t++) {
        if (t + 1 < NT) {
            issue_tile(t + 1);
            asm volatile("cp.async.wait_group 1;\n");
        } else {
            asm volatile("cp.async.wait_group 0;\n");
        }
        __syncthreads();

        const float* SA = smg + (t & 1) * 2 * TILE_F;
        const float* SB = SA + TILE_F;

#pragma unroll
        for (int ks = 0; ks < 4; ks++) {
            const int kb = ks * 8 + tig;

            if (TRIPLE) {
                uint32_t bhi[4][2], blo[4][2];
#pragma unroll
                for (int ni = 0; ni < 4; ni++) {
                    const int nr = wn + ni * 8 + gid;
                    split_tf32(SB[nr * ASTR + kb],     bhi[ni][0], blo[ni][0]);
                    split_tf32(SB[nr * ASTR + kb + 4], bhi[ni][1], blo[ni][1]);
                }
#pragma unroll
                for (int mi = 0; mi < 4; mi++) {
                    const int mr = wm + mi * 16 + gid;
                    uint32_t ahi[4], alo[4];
                    split_tf32(SA[mr * ASTR + kb],           ahi[0], alo[0]);
                    split_tf32(SA[(mr + 8) * ASTR + kb],     ahi[1], alo[1]);
                    split_tf32(SA[mr * ASTR + kb + 4],       ahi[2], alo[2]);
                    split_tf32(SA[(mr + 8) * ASTR + kb + 4], ahi[3], alo[3]);
#pragma unroll
                    for (int ni = 0; ni < 4; ni++) {
                        mma_tf32(acc[mi][ni], ahi, bhi[ni]);  // hi*hi
                        mma_tf32(acc[mi][ni], ahi, blo[ni]);  // hi*lo
                        mma_tf32(acc[mi][ni], alo, bhi[ni]);  // lo*hi
                    }
                }
            } else {
                uint32_t bfr[4][2];
#pragma unroll
                for (int ni = 0; ni < 4; ni++) {
                    const int nr = wn + ni * 8 + gid;
                    bfr[ni][0] = cvt_tf32(SB[nr * ASTR + kb]);
                    bfr[ni][1] = cvt_tf32(SB[nr * ASTR + kb + 4]);
                }
#pragma unroll
                for (int mi = 0; mi < 4; mi++) {
                    const int mr = wm + mi * 16 + gid;
                    uint32_t afr[4];
                    afr[0] = cvt_tf32(SA[mr * ASTR + kb]);
                    afr[1] = cvt_tf32(SA[(mr + 8) * ASTR + kb]);
                    afr[2] = cvt_tf32(SA[mr * ASTR + kb + 4]);
                    afr[3] = cvt_tf32(SA[(mr + 8) * ASTR + kb + 4]);
#pragma unroll
                    for (int ni = 0; ni < 4; ni++)
                        mma_tf32(acc[mi][ni], afr, bfr[ni]);
                }
            }
        }
        __syncthreads();
    }

#pragma unroll
    for (int mi = 0; mi < 4; mi++) {
#pragma unroll
        for (int ni = 0; ni < 4; ni++) {
            const int row = bm + wm + mi * 16 + gid;
            const int col = bn + wn + ni * 8 + 2 * tig;
            const float b0 = bias[col];
            const float b1 = bias[col + 1];
            float2 v0 = { acc[mi][ni][0] + b0, acc[mi][ni][1] + b1 };
            float2 v1 = { acc[mi][ni][2] + b0, acc[mi][ni][3] + b1 };
            if (do_rope) {
                // each float2 is a rope pair (2i, 2i+1)
                const int i  = (col & (HD_ - 1)) >> 1;
                const int s0 = row & (S_ - 1);
                const int s1 = (row + 8) & (S_ - 1);
                float c0 = cosT[s0 * 64 + i], sn0 = sinT[s0 * 64 + i];
                float c1 = cosT[s1 * 64 + i], sn1 = sinT[s1 * 64 + i];
                float2 r0 = { v0.x * c0 - v0.y * sn0, v0.x * sn0 + v0.y * c0 };
                float2 r1 = { v1.x * c1 - v1.y * sn1, v1.x * sn1 + v1.y * c1 };
                v0 = r0; v1 = r1;
            }
            *(float2*)(C + (size_t)row * N + col)       = v0;
            *(float2*)(C + (size_t)(row + 8) * N + col) = v1;
        }
    }
}

__global__ __launch_bounds__(256) void sgemm_qkv(
    const float* __restrict__ A, GemmSet gs,
    const float* __restrict__ cosT, const float* __restrict__ sinT,
    int M, int N, int K)
{
    extern __shared__ __align__(16) float smg[];
    const int z = blockIdx.z;
    sgemm_body<false>(A, gs.W[z], gs.bias[z], gs.C[z], M, N, K, smg,
                      cosT, sinT, z != 2);
}

__global__ __launch_bounds__(256) void sgemm_one(
    const float* __restrict__ A, const float* __restrict__ W,
    const float* __restrict__ bias, float* __restrict__ C,
    int M, int N, int K)
{
    extern __shared__ __align__(16) float smg[];
    sgemm_body<true>(A, W, bias, C, M, N, K, smg, nullptr, nullptr, false);
}

// ===========================================================================
// Flash attention (causal) on tensor pipe, m16n8k8 tf32, single-pass.
// CTA = 128 threads (4 warps), q-tile 64 rows (warp w owns rows w*16..+15).
// Q fragments precomputed to registers once per CTA (no Qs LDS in kt loop).
// K and V stored in smem as pre-converted tf32 bit patterns.
// S-frag -> A-frag rearrangement via warp shfl (verified round 4).
// V transposed at load with XOR swizzle (conflict-free ST and LD).
// ===========================================================================
#define QSTRF 132
#define VSTRF 68
#define FLASH_SMEM ((2 * 64 * QSTRF + 128 * VSTRF) * 4)

__device__ __forceinline__ int vsw(int d, int key)
{
    return d * VSTRF + (key ^ (((d >> 3) & 3) << 3));
}

__global__ __launch_bounds__(128) void flash_kernel(
    const float* __restrict__ Qg, const float* __restrict__ Kg,
    const float* __restrict__ Vg, float* __restrict__ Og)
{
    extern __shared__ __align__(16) float sm[];
    float* Qs = sm;                       // [64][132] raw fp32 (transient)
    float* Ks = Qs + 64 * QSTRF;          // [64][132] tf32 bit patterns
    float* Vt = Ks + 64 * QSTRF;          // [128][68] swizzled tf32 bits

    const int tid  = threadIdx.x;
    const int warp = tid >> 5;
    const int lane = tid & 31;
    const int gid  = lane >> 2;      // 0..7
    const int tig  = lane & 3;       // 0..3
    const int wq   = warp * 16;      // warp's q-row base within tile
    const int qt   = blockIdx.x;
    const int h    = blockIdx.y;
    const int b    = blockIdx.z;

    const size_t base_bh = (size_t)b * S_ * D_ + (size_t)h * HD_;

    // ---- Load Q tile (64 x 128) ----
#pragma unroll
    for (int i = 0; i < 16; i++) {
        int idx = tid + i * 128;          // 0..2047 float4s
        int r   = idx >> 5;
        int dq  = (idx & 31) << 2;
        *(float4*)&Qs[r * QSTRF + dq] =
            *(const float4*)(Qg + base_bh + (size_t)(qt * 64 + r) * D_ + dq);
    }
    __syncthreads();

    // ---- Precompute Q A-fragments (tf32) once: qfr[ks][0..3] ----
    uint32_t qfr[16][4];
#pragma unroll
    for (int ks = 0; ks < 16; ks++) {
        const int kb = ks * 8 + tig;
        qfr[ks][0] = cvt_tf32(Qs[(wq + gid) * QSTRF + kb]);
        qfr[ks][1] = cvt_tf32(Qs[(wq + gid + 8) * QSTRF + kb]);
        qfr[ks][2] = cvt_tf32(Qs[(wq + gid) * QSTRF + kb + 4]);
        qfr[ks][3] = cvt_tf32(Qs[(wq + gid + 8) * QSTRF + kb + 4]);
    }

    // O accumulator fragments: 16 n-frags (d = nf*8 + 2*tig + {0,1})
    float ofr[16][4];
#pragma unroll
    for (int nf = 0; nf < 16; nf++)
#pragma unroll
        for (int r = 0; r < 4; r++) ofr[nf][r] = 0.0f;

    float m0 = -1e30f, m1 = -1e30f, l0 = 0.0f, l1 = 0.0f;
    const float scale = 0.08838834764831845f;   // 1/sqrt(128)

    for (int kt = 0; kt <= qt; kt++) {
        __syncthreads();   // previous tile's reads of Ks/Vt done

        // ---- Load K tile (64 x 128), cvt to tf32 bits at store ----
#pragma unroll
        for (int i = 0; i < 16; i++) {
            int idx = tid + i * 128;
            int r   = idx >> 5;
            int dq  = (idx & 31) << 2;
            float4 kv = *(const float4*)(Kg + base_bh +
                                         (size_t)(kt * 64 + r) * D_ + dq);
            float4 kb;
            kb.x = __uint_as_float(cvt_tf32(kv.x));
            kb.y = __uint_as_float(cvt_tf32(kv.y));
            kb.z = __uint_as_float(cvt_tf32(kv.z));
            kb.w = __uint_as_float(cvt_tf32(kv.w));
            *(float4*)&Ks[r * QSTRF + dq] = kb;
        }
        // ---- Load + transpose V tile -> Vt[d][key] (swizzled tf32 bits) ----
        for (int kk = warp; kk < 64; kk += 4) {
            const float* vrow = Vg + base_bh + (size_t)(kt * 64 + kk) * D_;
#pragma unroll
            for (int j = 0; j < 4; j++) {
                int d = lane + 32 * j;
                Vt[vsw(d, kk)] = __uint_as_float(cvt_tf32(vrow[d]));
            }
        }
        __syncthreads();

        // ---- S = Q K^T (single tf32), warp: 16 rows x 64 keys ----
        float sfr[8][4];
#pragma unroll
        for (int nf = 0; nf < 8; nf++)
#pragma unroll
            for (int r = 0; r < 4; r++) sfr[nf][r] = 0.0f;

#pragma unroll
        for (int ks = 0; ks < 16; ks++) {
            const int kb = ks * 8 + tig;
#pragma unroll
            for (int nf = 0; nf < 8; nf++) {
                uint32_t bfr[2];
                bfr[0] = __float_as_uint(Ks[(nf * 8 + gid) * QSTRF + kb]);
                bfr[1] = __float_as_uint(Ks[(nf * 8 + gid) * QSTRF + kb + 4]);
                mma_tf32(sfr[nf], qfr[ks], bfr);
            }
        }

        // ---- scale + causal mask (diag tile only) ----
        const bool diag = (kt == qt);
        const int qrow0 = qt * 64 + wq + gid;
        const int qrow1 = qrow0 + 8;
#pragma unroll
        for (int nf = 0; nf < 8; nf++) {
#pragma unroll
            for (int c = 0; c < 2; c++) {
                int key = kt * 64 + nf * 8 + 2 * tig + c;
                float v0 = sfr[nf][c] * scale;
                float v1 = sfr[nf][2 + c] * scale;
                if (diag && key > qrow0) v0 = -1e30f;
                if (diag && key > qrow1) v1 = -1e30f;
                sfr[nf][c]     = v0;
                sfr[nf][2 + c] = v1;
            }
        }

        // ---- online softmax (rows spread over 4 tig lanes) ----
        float mx0 = -1e30f, mx1 = -1e30f;
#pragma unroll
        for (int nf = 0; nf < 8; nf++) {
            mx0 = fmaxf(mx0, fmaxf(sfr[nf][0], sfr[nf][1]));
            mx1 = fmaxf(mx1, fmaxf(sfr[nf][2], sfr[nf][3]));
        }
        mx0 = fmaxf(mx0, __shfl_xor_sync(0xffffffffu, mx0, 1));
        mx0 = fmaxf(mx0, __shfl_xor_sync(0xffffffffu, mx0, 2));
        mx1 = fmaxf(mx1, __shfl_xor_sync(0xffffffffu, mx1, 1));
        mx1 = fmaxf(mx1, __shfl_xor_sync(0xffffffffu, mx1, 2));

        float mn0 = fmaxf(m0, mx0);
        float mn1 = fmaxf(m1, mx1);
        float rs0 = 0.0f, rs1 = 0.0f;
#pragma unroll
        for (int nf = 0; nf < 8; nf++) {
            sfr[nf][0] = __expf(sfr[nf][0] - mn0);
            sfr[nf][1] = __expf(sfr[nf][1] - mn0);
            sfr[nf][2] = __expf(sfr[nf][2] - mn1);
            sfr[nf][3] = __expf(sfr[nf][3] - mn1);
            rs0 += sfr[nf][0] + sfr[nf][1];
            rs1 += sfr[nf][2] + sfr[nf][3];
        }
        rs0 += __shfl_xor_sync(0xffffffffu, rs0, 1);
        rs0 += __shfl_xor_sync(0xffffffffu, rs0, 2);
        rs1 += __shfl_xor_sync(0xffffffffu, rs1, 1);
        rs1 += __shfl_xor_sync(0xffffffffu, rs1, 2);

        float c0 = __expf(m0 - mn0);
        float c1 = __expf(m1 - mn1);
        l0 = l0 * c0 + rs0;
        l1 = l1 * c1 + rs1;
        m0 = mn0;
        m1 = mn1;
#pragma unroll
        for (int nf = 0; nf < 16; nf++) {
            ofr[nf][0] *= c0; ofr[nf][1] *= c0;
            ofr[nf][2] *= c1; ofr[nf][3] *= c1;
        }

        // ---- PV: O += P @ V. A-frags of P from S-frags via shfl. ----
        const int srcA = (gid << 2) | (tig >> 1);
        const int srcB = srcA + 2;
#pragma unroll
        for (int ks = 0; ks < 8; ks++) {
            float p0 = sfr[ks][0], p1 = sfr[ks][1];
            float p2 = sfr[ks][2], p3 = sfr[ks][3];
            float t0 = __shfl_sync(0xffffffffu, p0, srcA);
            float t1 = __shfl_sync(0xffffffffu, p1, srcA);
            float u0 = __shfl_sync(0xffffffffu, p2, srcA);
            float u1 = __shfl_sync(0xffffffffu, p3, srcA);
            float v0 = __shfl_sync(0xffffffffu, p0, srcB);
            float v1 = __shfl_sync(0xffffffffu, p1, srcB);
            float w0 = __shfl_sync(0xffffffffu, p2, srcB);
            float w1 = __shfl_sync(0xffffffffu, p3, srcB);
            bool odd = (tig & 1);
            uint32_t afr[4];
            afr[0] = cvt_tf32(odd ? t1 : t0);
            afr[1] = cvt_tf32(odd ? u1 : u0);
            afr[2] = cvt_tf32(odd ? v1 : v0);
            afr[3] = cvt_tf32(odd ? w1 : w0);

            const int key = ks * 8 + tig;
#pragma unroll
            for (int nf = 0; nf < 16; nf++) {
                const int d = nf * 8 + gid;
                uint32_t bb[2];
                bb[0] = __float_as_uint(Vt[vsw(d, key)]);
                bb[1] = __float_as_uint(Vt[vsw(d, key + 4)]);
                mma_tf32(ofr[nf], afr, bb);
            }
        }
    }

    // ---- normalize + store ----
    float inv0 = 1.0f / l0;
    float inv1 = 1.0f / l1;
    const size_t r0 = base_bh + (size_t)(qt * 64 + wq + gid) * D_;
    const size_t r1 = base_bh + (size_t)(qt * 64 + wq + gid + 8) * D_;
#pragma unroll
    for (int nf = 0; nf < 16; nf++) {
        int col = nf * 8 + 2 * tig;
        float2 o0 = { ofr[nf][0] * inv0, ofr[nf][1] * inv0 };
        float2 o1 = { ofr[nf][2] * inv1, ofr[nf][3] * inv1 };
        *(float2*)(Og + r0 + col) = o0;
        *(float2*)(Og + r1 + col) = o1;
    }
}

// ---------------------------------------------------------------------------
extern "C" void kernel_launch(void* const* d_in, const int* in_sizes, int n_in,
                              void* d_out, int out_size)
{
    const float* x  = (const float*)d_in[0];
    const float* wq = (const float*)d_in[1];
    const float* bq = (const float*)d_in[2];
    const float* wk = (const float*)d_in[3];
    const float* bk = (const float*)d_in[4];
    const float* wv = (const float*)d_in[5];
    const float* bv = (const float*)d_in[6];
    const float* wo = (const float*)d_in[7];
    const float* bo = (const float*)d_in[8];
    const float* fc = (const float*)d_in[9];
    const float* fs = (const float*)d_in[10];
    float* out = (float*)d_out;

    float *q, *k, *v, *ctx;
    cudaGetSymbolAddress((void**)&q,   g_q);
    cudaGetSymbolAddress((void**)&k,   g_k);
    cudaGetSymbolAddress((void**)&v,   g_v);
    cudaGetSymbolAddress((void**)&ctx, g_ctx);

    const int M = B_ * S_;

    cudaFuncSetAttribute(sgemm_qkv,
                         cudaFuncAttributeMaxDynamicSharedMemorySize,
                         GEMM_SMEM);
    cudaFuncSetAttribute(sgemm_one,
                         cudaFuncAttributeMaxDynamicSharedMemorySize,
                         GEMM_SMEM);

    GemmSet gs;
    gs.W[0] = wq;  gs.W[1] = wk;  gs.W[2] = wv;
    gs.bias[0] = bq; gs.bias[1] = bk; gs.bias[2] = bv;
    gs.C[0] = q;  gs.C[1] = k;  gs.C[2] = v;

    dim3 gqkv(D_ / 128, M / 128, 3);
    sgemm_qkv<<<gqkv, 256, GEMM_SMEM>>>(x, gs, fc, fs, M, D_, D_);

    cudaFuncSetAttribute(flash_kernel,
                         cudaFuncAttributeMaxDynamicSharedMemorySize,
                         FLASH_SMEM);
    flash_kernel<<<dim3(S_ / 64, H_, B_), 128, FLASH_SMEM>>>(q, k, v, ctx);

    dim3 go(D_ / 128, M / 128);
    sgemm_one<<<go, 256, GEMM_SMEM>>>(ctx, wo, bo, out, M, D_, D_);
}